// round 5
// baseline (speedup 1.0000x reference)
#include <cuda_runtime.h>

// ---------------------------------------------------------------------------
// JEPAPointDecoder — full pipeline on GB300, fp32 SIMT.
//
// Shapes (fixed by the problem instance):
//   B=4, P=384, M=64, TOK=1024, C=128, R_CTX=R_PRED=12, k=8
//
// Key restructuring: EdgeConv first layer  msg@We1 = a_i + b_j  with
//   a_i = x_i @ (We1_top - We1_bot) + be1,   b_j = x_j @ We1_bot
// so layer-1 is per-point instead of per-edge (8x fewer MACs there).
// ---------------------------------------------------------------------------

#define BB     4
#define PP     384
#define MMH    64
#define TOKN   1024
#define CC     128
#define RR     12
#define KK     8
#define NCTX   (PP*RR)        // 4608 ctx points per batch
#define NPRED  (MMH*RR)       // 768 pred points per batch
#define NALL   (NCTX+NPRED)   // 5376
#define NC_TOT (BB*NCTX)      // 18432
#define NP_TOT (BB*NPRED)     // 3072
#define NA_TOT (BB*NALL)      // 21504

// ----------------------------- scratch ------------------------------------
__device__ float g_anchor[BB*3];
__device__ float g_ctx_feat[BB*PP*CC];
__device__ float g_pred_feat[BB*MMH*CC];
__device__ float g_xyz_ctx[NC_TOT*3];
__device__ float g_xyz_p[NP_TOT*3];
__device__ float g_xyz_all[NA_TOT*3];
__device__ float g_featAll[(size_t)NA_TOT*CC];
__device__ float g_a[(size_t)NA_TOT*CC];
__device__ float g_b[(size_t)NA_TOT*CC];
__device__ int   g_idx[NA_TOT*KK];
__device__ float g_Wab[131*256];
__device__ float g_bab[256];

// ----------------------------- helpers ------------------------------------
// row mapping of stage-local point index -> concatenated [B, NALL] row
template<int MODE>
__device__ __forceinline__ int mapOut(int i) {
    if (MODE == 0) return (i / NCTX)  * NALL + (i % NCTX);           // ctx
    if (MODE == 1) return (i / NPRED) * NALL + NCTX + (i % NPRED);   // pred
    return i;                                                        // global
}

__device__ __forceinline__ float sq3(float x, float y, float z) {
    // matches jnp.sum(v*v): square (rounded) then left-to-right add
    return __fadd_rn(__fadd_rn(__fmul_rn(x, x), __fmul_rn(y, y)), __fmul_rn(z, z));
}

// ----------------------------- anchors ------------------------------------
__global__ void k_anchor(const float* __restrict__ ctx_xyz) {
    int b = blockIdx.x, tid = threadIdx.x;
    __shared__ float sred[3][128];
    float sx = 0.f, sy = 0.f, sz = 0.f;
    for (int p = tid; p < PP; p += 128) {
        const float* q = &ctx_xyz[(b * PP + p) * 3];
        sx += q[0]; sy += q[1]; sz += q[2];
    }
    sred[0][tid] = sx; sred[1][tid] = sy; sred[2][tid] = sz;
    __syncthreads();
    for (int s = 64; s > 0; s >>= 1) {
        if (tid < s) {
            sred[0][tid] += sred[0][tid + s];
            sred[1][tid] += sred[1][tid + s];
            sred[2][tid] += sred[2][tid + s];
        }
        __syncthreads();
    }
    if (tid == 0) {
        g_anchor[b * 3 + 0] = __fdiv_rn(sred[0][0], (float)PP);
        g_anchor[b * 3 + 1] = __fdiv_rn(sred[1][0], (float)PP);
        g_anchor[b * 3 + 2] = __fdiv_rn(sred[2][0], (float)PP);
    }
}

// --------------------------- token projection -----------------------------
// out[r,c] = tokens[r,:] @ Wp[:,c] + bp[c].  8 rows / block, 128 threads (=c).
template<int WHICH>
__global__ void k_proj(const float* __restrict__ tokens,
                       const float* __restrict__ Wp,
                       const float* __restrict__ bp) {
    constexpr int RPB = 8;
    __shared__ float st[RPB * TOKN];              // 32 KB
    float* out = (WHICH == 0) ? g_ctx_feat : g_pred_feat;
    int r0 = blockIdx.x * RPB;
    for (int e = threadIdx.x; e < RPB * TOKN; e += 128)
        st[e] = tokens[(size_t)r0 * TOKN + e];
    __syncthreads();
    int c = threadIdx.x;
    float bb = bp[c];
    float acc[RPB];
#pragma unroll
    for (int r = 0; r < RPB; ++r) acc[r] = bb;
    for (int t = 0; t < TOKN; t += 4) {
        float w0 = Wp[(t + 0) * CC + c];
        float w1 = Wp[(t + 1) * CC + c];
        float w2 = Wp[(t + 2) * CC + c];
        float w3 = Wp[(t + 3) * CC + c];
#pragma unroll
        for (int r = 0; r < RPB; ++r) {
            float4 v = *(const float4*)&st[r * TOKN + t];
            acc[r] = fmaf(v.x, w0, acc[r]);
            acc[r] = fmaf(v.y, w1, acc[r]);
            acc[r] = fmaf(v.z, w2, acc[r]);
            acc[r] = fmaf(v.w, w3, acc[r]);
        }
    }
#pragma unroll
    for (int r = 0; r < RPB; ++r)
        out[(size_t)(r0 + r) * CC + c] = acc[r];
}

// --------------------------- Wab construction -----------------------------
__global__ void k_wab(const float* __restrict__ We1, const float* __restrict__ be1) {
    int t = blockIdx.x * 256 + threadIdx.x;
    if (t < 131 * 128) {
        int r = t >> 7, c = t & 127;
        float top = We1[r * CC + c];
        float bot = We1[(131 + r) * CC + c];
        g_Wab[r * 256 + c]       = __fsub_rn(top, bot);
        g_Wab[r * 256 + 128 + c] = bot;
    }
    if (t < 128) { g_bab[t] = be1[t]; g_bab[128 + t] = 0.f; }
}

// ------------------------------ xyz builders ------------------------------
__global__ void k_xyz_ctx(const float* __restrict__ ctx_xyz,
                          const float* __restrict__ noise) {
    int i = blockIdx.x * 128 + threadIdx.x;
    if (i >= NC_TOT) return;
    float nx = noise[i * 3 + 0], ny = noise[i * 3 + 1], nz = noise[i * 3 + 2];
    float denom = __fadd_rn(sqrtf(sq3(nx, ny, nz)), 1e-6f);
    int bp = i / RR;   // b*P + p
    g_xyz_ctx[i * 3 + 0] = __fadd_rn(ctx_xyz[bp * 3 + 0], __fmul_rn(__fdiv_rn(nx, denom), 0.02f));
    g_xyz_ctx[i * 3 + 1] = __fadd_rn(ctx_xyz[bp * 3 + 1], __fmul_rn(__fdiv_rn(ny, denom), 0.02f));
    g_xyz_ctx[i * 3 + 2] = __fadd_rn(ctx_xyz[bp * 3 + 2], __fmul_rn(__fdiv_rn(nz, denom), 0.02f));
}

__global__ void k_xyz_pred(const float* __restrict__ noise) {
    int i = blockIdx.x * 128 + threadIdx.x;
    if (i >= NP_TOT) return;
    float nx = noise[i * 3 + 0], ny = noise[i * 3 + 1], nz = noise[i * 3 + 2];
    float denom = __fadd_rn(sqrtf(sq3(nx, ny, nz)), 1e-6f);
    int b = i / NPRED;
    g_xyz_p[i * 3 + 0] = __fadd_rn(g_anchor[b * 3 + 0], __fmul_rn(__fdiv_rn(nx, denom), 0.05f));
    g_xyz_p[i * 3 + 1] = __fadd_rn(g_anchor[b * 3 + 1], __fmul_rn(__fdiv_rn(ny, denom), 0.05f));
    g_xyz_p[i * 3 + 2] = __fadd_rn(g_anchor[b * 3 + 2], __fmul_rn(__fdiv_rn(nz, denom), 0.05f));
}

// --------------------------------- kNN -------------------------------------
// Whole batch in dynamic smem as float4 (x,y,z,|x|^2); each thread = 1 query,
// register top-8 sorted insertion, strict '<' reproduces top_k tie-break.
template<int STAGE>  // 0: ctx (N=4608), 2: global (N=5376)
__global__ void k_knn_batch() {
    constexpr int NB = (STAGE == 0) ? NCTX : NALL;
    extern __shared__ float4 sp[];
    const float* xyz = (STAGE == 0) ? g_xyz_ctx : g_xyz_all;
    int b = blockIdx.y;
    int base = b * NB;
    for (int j = threadIdx.x; j < NB; j += blockDim.x) {
        float x = xyz[(base + j) * 3 + 0];
        float y = xyz[(base + j) * 3 + 1];
        float z = xyz[(base + j) * 3 + 2];
        sp[j] = make_float4(x, y, z, sq3(x, y, z));
    }
    __syncthreads();
    int q = blockIdx.x * blockDim.x + threadIdx.x;   // grid sized exactly
    float4 pq = sp[q];
    float bd[KK]; int bi[KK];
#pragma unroll
    for (int s = 0; s < KK; ++s) { bd[s] = 3.0e38f; bi[s] = 0; }
    for (int j = 0; j < NB; ++j) {
        float4 pj = sp[j];
        float dot = __fmul_rn(pq.x, pj.x);
        dot = __fmaf_rn(pq.y, pj.y, dot);
        dot = __fmaf_rn(pq.z, pj.z, dot);
        float d2 = __fsub_rn(__fadd_rn(pq.w, pj.w), __fmul_rn(2.0f, dot));
        if (j != q && d2 < bd[KK - 1]) {
            int pos = KK - 1;
#pragma unroll
            for (int s = KK - 1; s > 0; --s) {
                if (d2 < bd[s - 1]) { bd[s] = bd[s - 1]; bi[s] = bi[s - 1]; pos = s - 1; }
            }
            bd[pos] = d2; bi[pos] = j;
        }
    }
#pragma unroll
    for (int s = 0; s < KK; ++s)
        g_idx[(base + q) * KK + s] = base + bi[s];
}

// tiny 12-point graphs: one thread per query point
__global__ void k_knn_pred() {
    int i = blockIdx.x * 128 + threadIdx.x;
    if (i >= NP_TOT) return;
    int base = (i / RR) * RR;
    int lr = i - base;
    float qx = g_xyz_p[i * 3 + 0], qy = g_xyz_p[i * 3 + 1], qz = g_xyz_p[i * 3 + 2];
    float qsq = sq3(qx, qy, qz);
    float bd[KK]; int bi[KK];
#pragma unroll
    for (int s = 0; s < KK; ++s) { bd[s] = 3.0e38f; bi[s] = 0; }
    for (int j = 0; j < RR; ++j) {
        if (j == lr) continue;
        int jj = base + j;
        float px = g_xyz_p[jj * 3 + 0], py = g_xyz_p[jj * 3 + 1], pz = g_xyz_p[jj * 3 + 2];
        float psq = sq3(px, py, pz);
        float dot = __fmul_rn(qx, px);
        dot = __fmaf_rn(qy, py, dot);
        dot = __fmaf_rn(qz, pz, dot);
        float d2 = __fsub_rn(__fadd_rn(qsq, psq), __fmul_rn(2.0f, dot));
        if (d2 < bd[KK - 1]) {
            int pos = KK - 1;
#pragma unroll
            for (int s = KK - 1; s > 0; --s) {
                if (d2 < bd[s - 1]) { bd[s] = bd[s - 1]; bi[s] = bi[s - 1]; pos = s - 1; }
            }
            bd[pos] = d2; bi[pos] = j;
        }
    }
#pragma unroll
    for (int s = 0; s < KK; ++s)
        g_idx[i * KK + s] = base + bi[s];
}

// ------------------------- per-point a/b projection ------------------------
// x_i = [feat_i (128), xyz_i (3)];  [a_i | b_i] = x_i @ Wab + [be1 | 0]
template<int MODE>   // 0 ctx, 1 pred, 2 global
__global__ void k_ab() {
    constexpr int PTS = 16;
    __shared__ float sx[PTS][132];
    const float* feat = (MODE == 0) ? g_ctx_feat : (MODE == 1) ? g_pred_feat : g_featAll;
    const float* xyz  = (MODE == 0) ? g_xyz_ctx  : (MODE == 1) ? g_xyz_p    : g_xyz_all;
    int i0 = blockIdx.x * PTS;
    for (int e = threadIdx.x; e < PTS * 131; e += 256) {
        int p = e / 131, t = e - p * 131;
        int i = i0 + p;
        int fr = (MODE == 2) ? i : (i / RR);
        sx[p][t] = (t < CC) ? feat[(size_t)fr * CC + t] : xyz[i * 3 + (t - CC)];
    }
    __syncthreads();
    int col = threadIdx.x;                // 0..255
    float bb = g_bab[col];
    float acc[PTS];
#pragma unroll
    for (int p = 0; p < PTS; ++p) acc[p] = bb;
    for (int r = 0; r < 128; r += 4) {
        float w0 = g_Wab[(r + 0) * 256 + col];
        float w1 = g_Wab[(r + 1) * 256 + col];
        float w2 = g_Wab[(r + 2) * 256 + col];
        float w3 = g_Wab[(r + 3) * 256 + col];
#pragma unroll
        for (int p = 0; p < PTS; ++p) {
            float4 v = *(const float4*)&sx[p][r];
            acc[p] = fmaf(v.x, w0, acc[p]);
            acc[p] = fmaf(v.y, w1, acc[p]);
            acc[p] = fmaf(v.z, w2, acc[p]);
            acc[p] = fmaf(v.w, w3, acc[p]);
        }
    }
    for (int r = 128; r < 131; ++r) {
        float w = g_Wab[r * 256 + col];
#pragma unroll
        for (int p = 0; p < PTS; ++p) acc[p] = fmaf(sx[p][r], w, acc[p]);
    }
#pragma unroll
    for (int p = 0; p < PTS; ++p) {
        int i = i0 + p;
        if (col < CC) g_a[(size_t)i * CC + col] = acc[p];
        else          g_b[(size_t)i * CC + (col - CC)] = acc[p];
    }
}

// --------------------- EdgeConv layer 2 + max aggregate --------------------
// out[i,c] = max_j ( relu(a_i + b_{n_j}) @ We2[:,c] ) + be2[c]
// 8 points/block, 128 threads (=c). hidden transposed in smem (stride 68)
// so inner loop reads it as broadcast float4; 64 register accumulators.
template<int MODE>
__global__ void __launch_bounds__(128) k_edge(const float* __restrict__ We2,
                                              const float* __restrict__ be2) {
    constexpr int PTS = 8;
    __shared__ float shid[128 * 68];      // [h][e], e = p*8+j, padded stride 68
    int i0 = blockIdx.x * PTS;
    int tid = threadIdx.x;
#pragma unroll
    for (int p = 0; p < PTS; ++p) {
        int i = i0 + p;
        float av = g_a[(size_t)i * CC + tid];
#pragma unroll
        for (int j = 0; j < KK; ++j) {
            int nb = g_idx[i * KK + j];
            float bv = g_b[(size_t)nb * CC + tid];
            shid[tid * 68 + p * KK + j] = fmaxf(__fadd_rn(av, bv), 0.f);
        }
    }
    __syncthreads();
    float acc[64];
#pragma unroll
    for (int e = 0; e < 64; ++e) acc[e] = 0.f;
#pragma unroll 2
    for (int h = 0; h < 128; ++h) {
        float w = We2[h * CC + tid];
        const float4* hp = (const float4*)&shid[h * 68];
#pragma unroll
        for (int e4 = 0; e4 < 16; ++e4) {
            float4 v = hp[e4];
            acc[e4 * 4 + 0] = fmaf(v.x, w, acc[e4 * 4 + 0]);
            acc[e4 * 4 + 1] = fmaf(v.y, w, acc[e4 * 4 + 1]);
            acc[e4 * 4 + 2] = fmaf(v.z, w, acc[e4 * 4 + 2]);
            acc[e4 * 4 + 3] = fmaf(v.w, w, acc[e4 * 4 + 3]);
        }
    }
    float bb = be2[tid];
#pragma unroll
    for (int p = 0; p < PTS; ++p) {
        float mx = acc[p * KK];
#pragma unroll
        for (int j = 1; j < KK; ++j) mx = fmaxf(mx, acc[p * KK + j]);
        g_featAll[(size_t)mapOut<MODE>(i0 + p) * CC + tid] = mx + bb;
    }
}

// ------------------------------ offset MLP ---------------------------------
// xyz_out = xyz_in + relu(feat @ W1 + b1) @ W2 + b2.   4 points/block.
template<int MODE>
__global__ void k_offset(const float* __restrict__ W1, const float* __restrict__ b1,
                         const float* __restrict__ W2, const float* __restrict__ b2,
                         float* __restrict__ outp) {
    __shared__ float sf[4][CC];
    __shared__ float sh[4][CC];
    int i0 = blockIdx.x * 4, tid = threadIdx.x;
#pragma unroll
    for (int p = 0; p < 4; ++p)
        sf[p][tid] = g_featAll[(size_t)mapOut<MODE>(i0 + p) * CC + tid];
    __syncthreads();
    float bb = b1[tid];
    float acc[4] = {bb, bb, bb, bb};
    for (int r = 0; r < CC; r += 4) {
        float w0 = W1[(r + 0) * CC + tid];
        float w1 = W1[(r + 1) * CC + tid];
        float w2 = W1[(r + 2) * CC + tid];
        float w3 = W1[(r + 3) * CC + tid];
#pragma unroll
        for (int p = 0; p < 4; ++p) {
            float4 v = *(const float4*)&sf[p][r];
            acc[p] = fmaf(v.x, w0, acc[p]);
            acc[p] = fmaf(v.y, w1, acc[p]);
            acc[p] = fmaf(v.z, w2, acc[p]);
            acc[p] = fmaf(v.w, w3, acc[p]);
        }
    }
#pragma unroll
    for (int p = 0; p < 4; ++p) sh[p][tid] = fmaxf(acc[p], 0.f);
    __syncthreads();
    int wp = tid >> 5, l = tid & 31;
    int i = i0 + wp;
    float s0 = 0.f, s1 = 0.f, s2 = 0.f;
    for (int h = l; h < CC; h += 32) {
        float hv = sh[wp][h];
        s0 = fmaf(hv, W2[h * 3 + 0], s0);
        s1 = fmaf(hv, W2[h * 3 + 1], s1);
        s2 = fmaf(hv, W2[h * 3 + 2], s2);
    }
#pragma unroll
    for (int off = 16; off; off >>= 1) {
        s0 += __shfl_down_sync(0xffffffffu, s0, off);
        s1 += __shfl_down_sync(0xffffffffu, s1, off);
        s2 += __shfl_down_sync(0xffffffffu, s2, off);
    }
    if (l == 0) {
        const float* xin = (MODE == 0) ? g_xyz_ctx : (MODE == 1) ? g_xyz_p : g_xyz_all;
        float* orow;
        if (MODE == 2) orow = outp + (size_t)i * 3;
        else           orow = g_xyz_all + (size_t)mapOut<MODE>(i) * 3;
        orow[0] = xin[i * 3 + 0] + s0 + b2[0];
        orow[1] = xin[i * 3 + 1] + s1 + b2[1];
        orow[2] = xin[i * 3 + 2] + s2 + b2[2];
    }
}

// ------------------------------- launcher ----------------------------------
extern "C" void kernel_launch(void* const* d_in, const int* in_sizes, int n_in,
                              void* d_out, int out_size) {
    const float* ctx_xyz     = (const float*)d_in[0];
    const float* ctx_tokens  = (const float*)d_in[1];
    const float* pred_tokens = (const float*)d_in[2];
    const float* noise_ctx   = (const float*)d_in[3];
    const float* noise_pred  = (const float*)d_in[4];
    const float* Wp  = (const float*)d_in[5];
    const float* bp  = (const float*)d_in[6];
    const float* We1 = (const float*)d_in[7];
    const float* be1 = (const float*)d_in[8];
    const float* We2 = (const float*)d_in[9];
    const float* be2 = (const float*)d_in[10];
    const float* Wc1 = (const float*)d_in[11];
    const float* bc1 = (const float*)d_in[12];
    const float* Wc2 = (const float*)d_in[13];
    const float* bc2 = (const float*)d_in[14];
    const float* Wq1 = (const float*)d_in[15];
    const float* bq1 = (const float*)d_in[16];
    const float* Wq2 = (const float*)d_in[17];
    const float* bq2 = (const float*)d_in[18];
    const float* Wf1 = (const float*)d_in[19];
    const float* bf1 = (const float*)d_in[20];
    const float* Wf2 = (const float*)d_in[21];
    const float* bf2 = (const float*)d_in[22];
    (void)in_sizes; (void)n_in; (void)out_size;
    float* out = (float*)d_out;

    cudaFuncSetAttribute(k_knn_batch<0>, cudaFuncAttributeMaxDynamicSharedMemorySize, NCTX * 16);
    cudaFuncSetAttribute(k_knn_batch<2>, cudaFuncAttributeMaxDynamicSharedMemorySize, NALL * 16);

    // ---- setup ----
    k_anchor<<<BB, 128>>>(ctx_xyz);
    k_proj<0><<<BB * PP / 8, 128>>>(ctx_tokens, Wp, bp);
    k_proj<1><<<BB * MMH / 8, 128>>>(pred_tokens, Wp, bp);
    k_wab<<<(131 * 128 + 255) / 256, 256>>>(We1, be1);
    k_xyz_ctx<<<NC_TOT / 128, 128>>>(ctx_xyz, noise_ctx);
    k_xyz_pred<<<NP_TOT / 128, 128>>>(noise_pred);

    // ---- context branch ----
    k_knn_batch<0><<<dim3(NCTX / 128, BB), 128, NCTX * 16>>>();
    k_ab<0><<<NC_TOT / 16, 256>>>();
    k_edge<0><<<NC_TOT / 8, 128>>>(We2, be2);
    k_offset<0><<<NC_TOT / 4, 128>>>(Wc1, bc1, Wc2, bc2, nullptr);

    // ---- prediction branch ----
    k_knn_pred<<<NP_TOT / 128, 128>>>();
    k_ab<1><<<NP_TOT / 16, 256>>>();
    k_edge<1><<<NP_TOT / 8, 128>>>(We2, be2);
    k_offset<1><<<NP_TOT / 4, 128>>>(Wq1, bq1, Wq2, bq2, nullptr);

    // ---- global refinement ----
    k_knn_batch<2><<<dim3(NALL / 128, BB), 128, NALL * 16>>>();
    k_ab<2><<<NA_TOT / 16, 256>>>();
    k_edge<2><<<NA_TOT / 8, 128>>>(We2, be2);
    k_offset<2><<<NA_TOT / 4, 128>>>(Wf1, bf1, Wf2, bf2, out);
}

// round 7
// speedup vs baseline: 1.0899x; 1.0899x over previous
#include <cuda_runtime.h>

// ---------------------------------------------------------------------------
// JEPAPointDecoder — full pipeline on GB300, fp32 with packed f32x2 FMA.
// (Resubmit of R5: prior round died to a broker/container infra failure
//  before any compile or run feedback; kernel itself is unmeasured.)
//
// Shapes: B=4, P=384, M=64, TOK=1024, C=128, R=12, k=8
//
// EdgeConv layer-1 factorization:  msg@We1 = a_i + b_j  with
//   a_i = x_i @ (We1_top - We1_bot) + be1,   b_j = x_j @ We1_bot
// sm_103a note: 3-reg FFMA is half-rate (rt=2); fma.rn.f32x2 restores full
// fp32 rate — used in all matmul inner loops.
// ---------------------------------------------------------------------------

#define BB     4
#define PP     384
#define MMH    64
#define TOKN   1024
#define CC     128
#define RR     12
#define KK     8
#define NCTX   (PP*RR)        // 4608
#define NPRED  (MMH*RR)       // 768
#define NALL   (NCTX+NPRED)   // 5376
#define NC_TOT (BB*NCTX)      // 18432
#define NP_TOT (BB*NPRED)     // 3072
#define NA_TOT (BB*NALL)      // 21504

// ----------------------------- scratch ------------------------------------
__device__ float g_anchor[BB*3];
__device__ float g_ctx_feat[BB*PP*CC];
__device__ float g_pred_feat[BB*MMH*CC];
__device__ float g_xyz_ctx[NC_TOT*3];
__device__ float g_xyz_p[NP_TOT*3];
__device__ float g_xyz_all[NA_TOT*3];
__device__ float g_featAll[(size_t)NA_TOT*CC];
__device__ float g_a[(size_t)NA_TOT*CC];
__device__ float g_b[(size_t)NA_TOT*CC];
__device__ int   g_idx[NA_TOT*KK];
__device__ float g_Wab[131*256];
__device__ float g_bab[256];

// --------------------------- f32x2 primitives ------------------------------
typedef unsigned long long u64;

__device__ __forceinline__ void ffma2(u64& d, u64 a, u64 b) {
    asm("fma.rn.f32x2 %0, %1, %2, %0;" : "+l"(d) : "l"(a), "l"(b));
}
__device__ __forceinline__ u64 pack2(float lo, float hi) {
    u64 r;
    unsigned int a = __float_as_uint(lo), b = __float_as_uint(hi);
    asm("mov.b64 %0, {%1, %2};" : "=l"(r) : "r"(a), "r"(b));
    return r;
}
__device__ __forceinline__ float2 unpack2(u64 v) {
    unsigned int a, b;
    asm("mov.b64 {%0, %1}, %2;" : "=r"(a), "=r"(b) : "l"(v));
    return make_float2(__uint_as_float(a), __uint_as_float(b));
}

// ----------------------------- helpers ------------------------------------
template<int MODE>
__device__ __forceinline__ int mapOut(int i) {
    if (MODE == 0) return (i / NCTX)  * NALL + (i % NCTX);           // ctx
    if (MODE == 1) return (i / NPRED) * NALL + NCTX + (i % NPRED);   // pred
    return i;                                                        // global
}

__device__ __forceinline__ float sq3(float x, float y, float z) {
    return __fadd_rn(__fadd_rn(__fmul_rn(x, x), __fmul_rn(y, y)), __fmul_rn(z, z));
}

// ----------------------------- anchors ------------------------------------
__global__ void k_anchor(const float* __restrict__ ctx_xyz) {
    int b = blockIdx.x, tid = threadIdx.x;
    __shared__ float sred[3][128];
    float sx = 0.f, sy = 0.f, sz = 0.f;
    for (int p = tid; p < PP; p += 128) {
        const float* q = &ctx_xyz[(b * PP + p) * 3];
        sx += q[0]; sy += q[1]; sz += q[2];
    }
    sred[0][tid] = sx; sred[1][tid] = sy; sred[2][tid] = sz;
    __syncthreads();
    for (int s = 64; s > 0; s >>= 1) {
        if (tid < s) {
            sred[0][tid] += sred[0][tid + s];
            sred[1][tid] += sred[1][tid + s];
            sred[2][tid] += sred[2][tid + s];
        }
        __syncthreads();
    }
    if (tid == 0) {
        g_anchor[b * 3 + 0] = __fdiv_rn(sred[0][0], (float)PP);
        g_anchor[b * 3 + 1] = __fdiv_rn(sred[1][0], (float)PP);
        g_anchor[b * 3 + 2] = __fdiv_rn(sred[2][0], (float)PP);
    }
}

// --------------------------- token projection -----------------------------
// out[r,c] = tokens[r,:] @ Wp[:,c] + bp[c].  8 rows/block, 128 threads (=c).
// f32x2: lo lane = even-t partial sum, hi lane = odd-t partial sum.
template<int WHICH>
__global__ void k_proj(const float* __restrict__ tokens,
                       const float* __restrict__ Wp,
                       const float* __restrict__ bp) {
    constexpr int RPB = 8;
    __shared__ __align__(16) float st[RPB * TOKN];        // 32 KB
    float* out = (WHICH == 0) ? g_ctx_feat : g_pred_feat;
    int r0 = blockIdx.x * RPB;
    for (int e = threadIdx.x; e < RPB * TOKN; e += 128)
        st[e] = tokens[(size_t)r0 * TOKN + e];
    __syncthreads();
    int c = threadIdx.x;
    float bb = bp[c];
    u64 acc[RPB];
#pragma unroll
    for (int r = 0; r < RPB; ++r) acc[r] = pack2(bb, 0.f);
    for (int t = 0; t < TOKN; t += 4) {
        float w0 = Wp[(t + 0) * CC + c];
        float w1 = Wp[(t + 1) * CC + c];
        float w2 = Wp[(t + 2) * CC + c];
        float w3 = Wp[(t + 3) * CC + c];
        u64 ww01 = pack2(w0, w1);
        u64 ww23 = pack2(w2, w3);
#pragma unroll
        for (int r = 0; r < RPB; ++r) {
            ulonglong2 v = *(const ulonglong2*)&st[r * TOKN + t];
            ffma2(acc[r], v.x, ww01);
            ffma2(acc[r], v.y, ww23);
        }
    }
#pragma unroll
    for (int r = 0; r < RPB; ++r) {
        float2 u = unpack2(acc[r]);
        out[(size_t)(r0 + r) * CC + c] = u.x + u.y;
    }
}

// --------------------------- Wab construction -----------------------------
__global__ void k_wab(const float* __restrict__ We1, const float* __restrict__ be1) {
    int t = blockIdx.x * 256 + threadIdx.x;
    if (t < 131 * 128) {
        int r = t >> 7, c = t & 127;
        float top = We1[r * CC + c];
        float bot = We1[(131 + r) * CC + c];
        g_Wab[r * 256 + c]       = __fsub_rn(top, bot);
        g_Wab[r * 256 + 128 + c] = bot;
    }
    if (t < 128) { g_bab[t] = be1[t]; g_bab[128 + t] = 0.f; }
}

// ------------------------------ xyz builders ------------------------------
__global__ void k_xyz_ctx(const float* __restrict__ ctx_xyz,
                          const float* __restrict__ noise) {
    int i = blockIdx.x * 128 + threadIdx.x;
    if (i >= NC_TOT) return;
    float nx = noise[i * 3 + 0], ny = noise[i * 3 + 1], nz = noise[i * 3 + 2];
    float denom = __fadd_rn(sqrtf(sq3(nx, ny, nz)), 1e-6f);
    int bp = i / RR;
    g_xyz_ctx[i * 3 + 0] = __fadd_rn(ctx_xyz[bp * 3 + 0], __fmul_rn(__fdiv_rn(nx, denom), 0.02f));
    g_xyz_ctx[i * 3 + 1] = __fadd_rn(ctx_xyz[bp * 3 + 1], __fmul_rn(__fdiv_rn(ny, denom), 0.02f));
    g_xyz_ctx[i * 3 + 2] = __fadd_rn(ctx_xyz[bp * 3 + 2], __fmul_rn(__fdiv_rn(nz, denom), 0.02f));
}

__global__ void k_xyz_pred(const float* __restrict__ noise) {
    int i = blockIdx.x * 128 + threadIdx.x;
    if (i >= NP_TOT) return;
    float nx = noise[i * 3 + 0], ny = noise[i * 3 + 1], nz = noise[i * 3 + 2];
    float denom = __fadd_rn(sqrtf(sq3(nx, ny, nz)), 1e-6f);
    int b = i / NPRED;
    g_xyz_p[i * 3 + 0] = __fadd_rn(g_anchor[b * 3 + 0], __fmul_rn(__fdiv_rn(nx, denom), 0.05f));
    g_xyz_p[i * 3 + 1] = __fadd_rn(g_anchor[b * 3 + 1], __fmul_rn(__fdiv_rn(ny, denom), 0.05f));
    g_xyz_p[i * 3 + 2] = __fadd_rn(g_anchor[b * 3 + 2], __fmul_rn(__fdiv_rn(nz, denom), 0.05f));
}

// --------------------------------- kNN -------------------------------------
// 512 threads/block: 128 queries x 4 candidate slices, merged in smem.
// Strict '<' insertion + slice order == ascending j preserves top_k tie-break.
template<int STAGE>  // 0: ctx (N=4608), 2: global (N=5376)
__global__ void __launch_bounds__(512) k_knn_batch() {
    constexpr int NB = (STAGE == 0) ? NCTX : NALL;
    constexpr int SL = NB / 4;
    extern __shared__ unsigned char dynsm[];
    float4* sp = (float4*)dynsm;
    float*  md = (float*)(sp + NB);          // [32][128]  (e-major)
    int*    mi = (int*)(md + 32 * 128);      // [32][128]
    const float* xyz = (STAGE == 0) ? g_xyz_ctx : g_xyz_all;
    int b = blockIdx.y;
    int base = b * NB;
    for (int j = threadIdx.x; j < NB; j += 512) {
        float x = xyz[(base + j) * 3 + 0];
        float y = xyz[(base + j) * 3 + 1];
        float z = xyz[(base + j) * 3 + 2];
        sp[j] = make_float4(x, y, z, sq3(x, y, z));
    }
    __syncthreads();
    int qi = threadIdx.x & 127, slice = threadIdx.x >> 7;
    int q = blockIdx.x * 128 + qi;
    float4 pq = sp[q];
    float bd[KK]; int bi[KK];
#pragma unroll
    for (int s = 0; s < KK; ++s) { bd[s] = 3.0e38f; bi[s] = 0; }
    int j1 = slice * SL + SL;
    for (int j = slice * SL; j < j1; ++j) {
        float4 pj = sp[j];
        float dot = __fmul_rn(pq.x, pj.x);
        dot = __fmaf_rn(pq.y, pj.y, dot);
        dot = __fmaf_rn(pq.z, pj.z, dot);
        float d2 = __fsub_rn(__fadd_rn(pq.w, pj.w), __fmul_rn(2.0f, dot));
        if (j != q && d2 < bd[KK - 1]) {
            int pos = KK - 1;
#pragma unroll
            for (int s = KK - 1; s > 0; --s) {
                if (d2 < bd[s - 1]) { bd[s] = bd[s - 1]; bi[s] = bi[s - 1]; pos = s - 1; }
            }
            bd[pos] = d2; bi[pos] = j;
        }
    }
#pragma unroll
    for (int s = 0; s < KK; ++s) {
        md[(slice * KK + s) * 128 + qi] = bd[s];
        mi[(slice * KK + s) * 128 + qi] = bi[s];
    }
    __syncthreads();
    if (slice == 0) {
        float fd[KK]; int fi[KK];
#pragma unroll
        for (int s = 0; s < KK; ++s) { fd[s] = 3.0e38f; fi[s] = 0; }
        for (int e = 0; e < 32; ++e) {
            float d = md[e * 128 + qi];
            int  ix = mi[e * 128 + qi];
            if (d < fd[KK - 1]) {
                int pos = KK - 1;
#pragma unroll
                for (int s = KK - 1; s > 0; --s) {
                    if (d < fd[s - 1]) { fd[s] = fd[s - 1]; fi[s] = fi[s - 1]; pos = s - 1; }
                }
                fd[pos] = d; fi[pos] = ix;
            }
        }
#pragma unroll
        for (int s = 0; s < KK; ++s)
            g_idx[(base + q) * KK + s] = base + fi[s];
    }
}

// tiny 12-point graphs: one thread per query point
__global__ void k_knn_pred() {
    int i = blockIdx.x * 128 + threadIdx.x;
    if (i >= NP_TOT) return;
    int base = (i / RR) * RR;
    int lr = i - base;
    float qx = g_xyz_p[i * 3 + 0], qy = g_xyz_p[i * 3 + 1], qz = g_xyz_p[i * 3 + 2];
    float qsq = sq3(qx, qy, qz);
    float bd[KK]; int bi[KK];
#pragma unroll
    for (int s = 0; s < KK; ++s) { bd[s] = 3.0e38f; bi[s] = 0; }
    for (int j = 0; j < RR; ++j) {
        if (j == lr) continue;
        int jj = base + j;
        float px = g_xyz_p[jj * 3 + 0], py = g_xyz_p[jj * 3 + 1], pz = g_xyz_p[jj * 3 + 2];
        float psq = sq3(px, py, pz);
        float dot = __fmul_rn(qx, px);
        dot = __fmaf_rn(qy, py, dot);
        dot = __fmaf_rn(qz, pz, dot);
        float d2 = __fsub_rn(__fadd_rn(qsq, psq), __fmul_rn(2.0f, dot));
        if (d2 < bd[KK - 1]) {
            int pos = KK - 1;
#pragma unroll
            for (int s = KK - 1; s > 0; --s) {
                if (d2 < bd[s - 1]) { bd[s] = bd[s - 1]; bi[s] = bi[s - 1]; pos = s - 1; }
            }
            bd[pos] = d2; bi[pos] = j;
        }
    }
#pragma unroll
    for (int s = 0; s < KK; ++s)
        g_idx[i * KK + s] = base + bi[s];
}

// ------------------------- per-point a/b projection ------------------------
// x_i = [feat_i(128), xyz_i(3)];  [a_i|b_i] = x_i @ Wab + [be1|0]
// f32x2 even/odd-K pairing, scalar tail for rows 128..130.
template<int MODE>   // 0 ctx, 1 pred, 2 global
__global__ void k_ab() {
    constexpr int PTS = 16;
    __shared__ __align__(16) float sx[PTS][132];
    const float* feat = (MODE == 0) ? g_ctx_feat : (MODE == 1) ? g_pred_feat : g_featAll;
    const float* xyz  = (MODE == 0) ? g_xyz_ctx  : (MODE == 1) ? g_xyz_p    : g_xyz_all;
    int i0 = blockIdx.x * PTS;
    for (int e = threadIdx.x; e < PTS * 131; e += 256) {
        int p = e / 131, t = e - p * 131;
        int i = i0 + p;
        int fr = (MODE == 2) ? i : (i / RR);
        sx[p][t] = (t < CC) ? feat[(size_t)fr * CC + t] : xyz[i * 3 + (t - CC)];
    }
    __syncthreads();
    int col = threadIdx.x;                // 0..255
    float bb = g_bab[col];
    u64 acc[PTS];
    float tacc[PTS];
    u64 init = pack2(bb, 0.f);
#pragma unroll
    for (int p = 0; p < PTS; ++p) { acc[p] = init; tacc[p] = 0.f; }
    for (int r = 0; r < 128; r += 2) {
        float w0 = g_Wab[(r + 0) * 256 + col];
        float w1 = g_Wab[(r + 1) * 256 + col];
        u64 ww = pack2(w0, w1);
#pragma unroll
        for (int p = 0; p < PTS; ++p) {
            u64 v = *(const u64*)&sx[p][r];
            ffma2(acc[p], v, ww);
        }
    }
#pragma unroll
    for (int r = 128; r < 131; ++r) {
        float w = g_Wab[r * 256 + col];
#pragma unroll
        for (int p = 0; p < PTS; ++p) tacc[p] = fmaf(sx[p][r], w, tacc[p]);
    }
#pragma unroll
    for (int p = 0; p < PTS; ++p) {
        float2 u = unpack2(acc[p]);
        float res = u.x + u.y + tacc[p];
        int i = i0 + p;
        if (col < CC) g_a[(size_t)i * CC + col] = res;
        else          g_b[(size_t)i * CC + (col - CC)] = res;
    }
}

// --------------------- EdgeConv layer 2 + max aggregate --------------------
// out[i,c] = max_j ( relu(a_i + b_{n_j}) @ We2[:,c] ) + be2[c]
// 8 points/block, 128 threads (=c). hidden edge-major in smem; edge pairs
// are contiguous -> f32x2 M-pairing with zero packing ops (bitwise exact).
template<int MODE>
__global__ void __launch_bounds__(128) k_edge(const float* __restrict__ We2,
                                              const float* __restrict__ be2) {
    constexpr int PTS = 8;
    __shared__ __align__(16) float shid[128 * 68];    // [h][e], stride 68
    int i0 = blockIdx.x * PTS;
    int tid = threadIdx.x;
#pragma unroll
    for (int p = 0; p < PTS; ++p) {
        int i = i0 + p;
        float av = g_a[(size_t)i * CC + tid];
#pragma unroll
        for (int j = 0; j < KK; ++j) {
            int nb = g_idx[i * KK + j];
            float bv = g_b[(size_t)nb * CC + tid];
            shid[tid * 68 + p * KK + j] = fmaxf(__fadd_rn(av, bv), 0.f);
        }
    }
    __syncthreads();
    u64 acc[32];
#pragma unroll
    for (int e = 0; e < 32; ++e) acc[e] = 0ull;
    for (int h = 0; h < 128; ++h) {
        float w = We2[h * CC + tid];
        u64 ww = pack2(w, w);
        const ulonglong2* hp = (const ulonglong2*)&shid[h * 68];
#pragma unroll
        for (int e = 0; e < 16; ++e) {
            ulonglong2 v = hp[e];
            ffma2(acc[2 * e + 0], v.x, ww);
            ffma2(acc[2 * e + 1], v.y, ww);
        }
    }
    float bb = be2[tid];
#pragma unroll
    for (int p = 0; p < PTS; ++p) {
        float2 v0 = unpack2(acc[p * 4 + 0]);
        float2 v1 = unpack2(acc[p * 4 + 1]);
        float2 v2 = unpack2(acc[p * 4 + 2]);
        float2 v3 = unpack2(acc[p * 4 + 3]);
        float mx = fmaxf(fmaxf(fmaxf(v0.x, v0.y), fmaxf(v1.x, v1.y)),
                         fmaxf(fmaxf(v2.x, v2.y), fmaxf(v3.x, v3.y)));
        g_featAll[(size_t)mapOut<MODE>(i0 + p) * CC + tid] = mx + bb;
    }
}

// ------------------------------ offset MLP ---------------------------------
// xyz_out = xyz_in + relu(feat @ W1 + b1) @ W2 + b2.   8 points/block.
template<int MODE>
__global__ void __launch_bounds__(128) k_offset(const float* __restrict__ W1,
                                                const float* __restrict__ b1,
                                                const float* __restrict__ W2,
                                                const float* __restrict__ b2,
                                                float* __restrict__ outp) {
    constexpr int PTS = 8;
    __shared__ __align__(16) float sf[PTS][CC];
    __shared__ float sh[PTS][CC];
    int i0 = blockIdx.x * PTS, tid = threadIdx.x;
#pragma unroll
    for (int p = 0; p < PTS; ++p)
        sf[p][tid] = g_featAll[(size_t)mapOut<MODE>(i0 + p) * CC + tid];
    __syncthreads();
    float bb = b1[tid];
    u64 acc[PTS];
    u64 init = pack2(bb, 0.f);
#pragma unroll
    for (int p = 0; p < PTS; ++p) acc[p] = init;
    for (int r = 0; r < CC; r += 2) {
        u64 ww = pack2(W1[(r + 0) * CC + tid], W1[(r + 1) * CC + tid]);
#pragma unroll
        for (int p = 0; p < PTS; ++p) {
            u64 v = *(const u64*)&sf[p][r];
            ffma2(acc[p], v, ww);
        }
    }
#pragma unroll
    for (int p = 0; p < PTS; ++p) {
        float2 u = unpack2(acc[p]);
        sh[p][tid] = fmaxf(u.x + u.y, 0.f);
    }
    __syncthreads();
    int wp0 = (tid >> 5) * 2, l = tid & 31;
#pragma unroll
    for (int t = 0; t < 2; ++t) {
        int wp = wp0 + t;
        int i = i0 + wp;
        float s0 = 0.f, s1 = 0.f, s2 = 0.f;
        for (int h = l; h < CC; h += 32) {
            float hv = sh[wp][h];
            s0 = fmaf(hv, W2[h * 3 + 0], s0);
            s1 = fmaf(hv, W2[h * 3 + 1], s1);
            s2 = fmaf(hv, W2[h * 3 + 2], s2);
        }
#pragma unroll
        for (int off = 16; off; off >>= 1) {
            s0 += __shfl_down_sync(0xffffffffu, s0, off);
            s1 += __shfl_down_sync(0xffffffffu, s1, off);
            s2 += __shfl_down_sync(0xffffffffu, s2, off);
        }
        if (l == 0) {
            const float* xin = (MODE == 0) ? g_xyz_ctx : (MODE == 1) ? g_xyz_p : g_xyz_all;
            float* orow;
            if (MODE == 2) orow = outp + (size_t)i * 3;
            else           orow = g_xyz_all + (size_t)mapOut<MODE>(i) * 3;
            orow[0] = xin[i * 3 + 0] + s0 + b2[0];
            orow[1] = xin[i * 3 + 1] + s1 + b2[1];
            orow[2] = xin[i * 3 + 2] + s2 + b2[2];
        }
    }
}

// ------------------------------- launcher ----------------------------------
extern "C" void kernel_launch(void* const* d_in, const int* in_sizes, int n_in,
                              void* d_out, int out_size) {
    const float* ctx_xyz     = (const float*)d_in[0];
    const float* ctx_tokens  = (const float*)d_in[1];
    const float* pred_tokens = (const float*)d_in[2];
    const float* noise_ctx   = (const float*)d_in[3];
    const float* noise_pred  = (const float*)d_in[4];
    const float* Wp  = (const float*)d_in[5];
    const float* bp  = (const float*)d_in[6];
    const float* We1 = (const float*)d_in[7];
    const float* be1 = (const float*)d_in[8];
    const float* We2 = (const float*)d_in[9];
    const float* be2 = (const float*)d_in[10];
    const float* Wc1 = (const float*)d_in[11];
    const float* bc1 = (const float*)d_in[12];
    const float* Wc2 = (const float*)d_in[13];
    const float* bc2 = (const float*)d_in[14];
    const float* Wq1 = (const float*)d_in[15];
    const float* bq1 = (const float*)d_in[16];
    const float* Wq2 = (const float*)d_in[17];
    const float* bq2 = (const float*)d_in[18];
    const float* Wf1 = (const float*)d_in[19];
    const float* bf1 = (const float*)d_in[20];
    const float* Wf2 = (const float*)d_in[21];
    const float* bf2 = (const float*)d_in[22];
    (void)in_sizes; (void)n_in; (void)out_size;
    float* out = (float*)d_out;

    constexpr int SM_KNN0 = NCTX * 16 + 32 * 128 * 8;   // 106496
    constexpr int SM_KNN2 = NALL * 16 + 32 * 128 * 8;   // 118784
    cudaFuncSetAttribute(k_knn_batch<0>, cudaFuncAttributeMaxDynamicSharedMemorySize, SM_KNN0);
    cudaFuncSetAttribute(k_knn_batch<2>, cudaFuncAttributeMaxDynamicSharedMemorySize, SM_KNN2);

    // ---- setup (ordered so heavy kernels land in the ncu-captured slots) ----
    k_anchor<<<BB, 128>>>(ctx_xyz);
    k_xyz_ctx<<<NC_TOT / 128, 128>>>(ctx_xyz, noise_ctx);
    k_xyz_pred<<<NP_TOT / 128, 128>>>(noise_pred);
    k_knn_batch<0><<<dim3(NCTX / 128, BB), 512, SM_KNN0>>>();
    k_proj<0><<<BB * PP / 8, 128>>>(ctx_tokens, Wp, bp);
    k_proj<1><<<BB * MMH / 8, 128>>>(pred_tokens, Wp, bp);
    k_wab<<<(131 * 128 + 255) / 256, 256>>>(We1, be1);

    // ---- context branch ----
    k_ab<0><<<NC_TOT / 16, 256>>>();
    k_edge<0><<<NC_TOT / 8, 128>>>(We2, be2);
    k_offset<0><<<NC_TOT / 8, 128>>>(Wc1, bc1, Wc2, bc2, nullptr);

    // ---- prediction branch ----
    k_knn_pred<<<NP_TOT / 128, 128>>>();
    k_ab<1><<<NP_TOT / 16, 256>>>();
    k_edge<1><<<NP_TOT / 8, 128>>>(We2, be2);
    k_offset<1><<<NP_TOT / 8, 128>>>(Wq1, bq1, Wq2, bq2, nullptr);

    // ---- global refinement ----
    k_knn_batch<2><<<dim3(NALL / 128, BB), 512, SM_KNN2>>>();
    k_ab<2><<<NA_TOT / 16, 256>>>();
    k_edge<2><<<NA_TOT / 8, 128>>>(We2, be2);
    k_offset<2><<<NA_TOT / 8, 128>>>(Wf1, bf1, Wf2, bf2, out);
}

// round 8
// speedup vs baseline: 1.1331x; 1.0397x over previous
#include <cuda_runtime.h>

// ---------------------------------------------------------------------------
// JEPAPointDecoder — full pipeline on GB300, fp32 with packed f32x2 FMA.
//
// Shapes: B=4, P=384, M=64, TOK=1024, C=128, R=12, k=8
//
// EdgeConv layer-1 factorization:  msg@We1 = a_i + b_j  with
//   a_i = x_i @ (We1_top - We1_bot) + be1,   b_j = x_j @ We1_bot
//
// R8: kNN rewritten — SoA points, f32x2-packed distances (2 cand/reg),
// 8 slices x 64 queries/block, merge buffers alias point smem (73.7/86 KB
// -> 3/2 blocks/SM), 4-candidate batches with min-precheck. Launches
// reordered so k_ab<0> is the 4th launch (the ncu-captured slot).
// ---------------------------------------------------------------------------

#define BB     4
#define PP     384
#define MMH    64
#define TOKN   1024
#define CC     128
#define RR     12
#define KK     8
#define NCTX   (PP*RR)        // 4608
#define NPRED  (MMH*RR)       // 768
#define NALL   (NCTX+NPRED)   // 5376
#define NC_TOT (BB*NCTX)      // 18432
#define NP_TOT (BB*NPRED)     // 3072
#define NA_TOT (BB*NALL)      // 21504

// ----------------------------- scratch ------------------------------------
__device__ float g_anchor[BB*3];
__device__ float g_ctx_feat[BB*PP*CC];
__device__ float g_pred_feat[BB*MMH*CC];
__device__ float g_xyz_ctx[NC_TOT*3];
__device__ float g_xyz_p[NP_TOT*3];
__device__ float g_xyz_all[NA_TOT*3];
__device__ float g_featAll[(size_t)NA_TOT*CC];
__device__ float g_a[(size_t)NA_TOT*CC];
__device__ float g_b[(size_t)NA_TOT*CC];
__device__ int   g_idx[NA_TOT*KK];
__device__ float g_Wab[131*256];
__device__ float g_bab[256];

// --------------------------- f32x2 primitives ------------------------------
typedef unsigned long long u64;

__device__ __forceinline__ void ffma2(u64& d, u64 a, u64 b) {
    asm("fma.rn.f32x2 %0, %1, %2, %0;" : "+l"(d) : "l"(a), "l"(b));
}
__device__ __forceinline__ u64 fma2v(u64 a, u64 b, u64 c) {
    u64 d;
    asm("fma.rn.f32x2 %0, %1, %2, %3;" : "=l"(d) : "l"(a), "l"(b), "l"(c));
    return d;
}
__device__ __forceinline__ u64 mulx2(u64 a, u64 b) {
    u64 d;
    asm("mul.rn.f32x2 %0, %1, %2;" : "=l"(d) : "l"(a), "l"(b));
    return d;
}
__device__ __forceinline__ u64 addx2(u64 a, u64 b) {
    u64 d;
    asm("add.rn.f32x2 %0, %1, %2;" : "=l"(d) : "l"(a), "l"(b));
    return d;
}
__device__ __forceinline__ u64 pack2(float lo, float hi) {
    u64 r;
    unsigned int a = __float_as_uint(lo), b = __float_as_uint(hi);
    asm("mov.b64 %0, {%1, %2};" : "=l"(r) : "r"(a), "r"(b));
    return r;
}
__device__ __forceinline__ float2 unpack2(u64 v) {
    unsigned int a, b;
    asm("mov.b64 {%0, %1}, %2;" : "=r"(a), "=r"(b) : "l"(v));
    return make_float2(__uint_as_float(a), __uint_as_float(b));
}

// ----------------------------- helpers ------------------------------------
template<int MODE>
__device__ __forceinline__ int mapOut(int i) {
    if (MODE == 0) return (i / NCTX)  * NALL + (i % NCTX);           // ctx
    if (MODE == 1) return (i / NPRED) * NALL + NCTX + (i % NPRED);   // pred
    return i;                                                        // global
}

__device__ __forceinline__ float sq3(float x, float y, float z) {
    return __fadd_rn(__fadd_rn(__fmul_rn(x, x), __fmul_rn(y, y)), __fmul_rn(z, z));
}

// ----------------------------- anchors ------------------------------------
__global__ void k_anchor(const float* __restrict__ ctx_xyz) {
    int b = blockIdx.x, tid = threadIdx.x;
    __shared__ float sred[3][128];
    float sx = 0.f, sy = 0.f, sz = 0.f;
    for (int p = tid; p < PP; p += 128) {
        const float* q = &ctx_xyz[(b * PP + p) * 3];
        sx += q[0]; sy += q[1]; sz += q[2];
    }
    sred[0][tid] = sx; sred[1][tid] = sy; sred[2][tid] = sz;
    __syncthreads();
    for (int s = 64; s > 0; s >>= 1) {
        if (tid < s) {
            sred[0][tid] += sred[0][tid + s];
            sred[1][tid] += sred[1][tid + s];
            sred[2][tid] += sred[2][tid + s];
        }
        __syncthreads();
    }
    if (tid == 0) {
        g_anchor[b * 3 + 0] = __fdiv_rn(sred[0][0], (float)PP);
        g_anchor[b * 3 + 1] = __fdiv_rn(sred[1][0], (float)PP);
        g_anchor[b * 3 + 2] = __fdiv_rn(sred[2][0], (float)PP);
    }
}

// --------------------------- token projection -----------------------------
template<int WHICH>
__global__ void k_proj(const float* __restrict__ tokens,
                       const float* __restrict__ Wp,
                       const float* __restrict__ bp) {
    constexpr int RPB = 8;
    __shared__ __align__(16) float st[RPB * TOKN];        // 32 KB
    float* out = (WHICH == 0) ? g_ctx_feat : g_pred_feat;
    int r0 = blockIdx.x * RPB;
    for (int e = threadIdx.x; e < RPB * TOKN; e += 128)
        st[e] = tokens[(size_t)r0 * TOKN + e];
    __syncthreads();
    int c = threadIdx.x;
    float bb = bp[c];
    u64 acc[RPB];
#pragma unroll
    for (int r = 0; r < RPB; ++r) acc[r] = pack2(bb, 0.f);
    for (int t = 0; t < TOKN; t += 4) {
        float w0 = Wp[(t + 0) * CC + c];
        float w1 = Wp[(t + 1) * CC + c];
        float w2 = Wp[(t + 2) * CC + c];
        float w3 = Wp[(t + 3) * CC + c];
        u64 ww01 = pack2(w0, w1);
        u64 ww23 = pack2(w2, w3);
#pragma unroll
        for (int r = 0; r < RPB; ++r) {
            ulonglong2 v = *(const ulonglong2*)&st[r * TOKN + t];
            ffma2(acc[r], v.x, ww01);
            ffma2(acc[r], v.y, ww23);
        }
    }
#pragma unroll
    for (int r = 0; r < RPB; ++r) {
        float2 u = unpack2(acc[r]);
        out[(size_t)(r0 + r) * CC + c] = u.x + u.y;
    }
}

// --------------------------- Wab construction -----------------------------
__global__ void k_wab(const float* __restrict__ We1, const float* __restrict__ be1) {
    int t = blockIdx.x * 256 + threadIdx.x;
    if (t < 131 * 128) {
        int r = t >> 7, c = t & 127;
        float top = We1[r * CC + c];
        float bot = We1[(131 + r) * CC + c];
        g_Wab[r * 256 + c]       = __fsub_rn(top, bot);
        g_Wab[r * 256 + 128 + c] = bot;
    }
    if (t < 128) { g_bab[t] = be1[t]; g_bab[128 + t] = 0.f; }
}

// ------------------------------ xyz builders ------------------------------
__global__ void k_xyz_ctx(const float* __restrict__ ctx_xyz,
                          const float* __restrict__ noise) {
    int i = blockIdx.x * 128 + threadIdx.x;
    if (i >= NC_TOT) return;
    float nx = noise[i * 3 + 0], ny = noise[i * 3 + 1], nz = noise[i * 3 + 2];
    float denom = __fadd_rn(sqrtf(sq3(nx, ny, nz)), 1e-6f);
    int bp = i / RR;
    g_xyz_ctx[i * 3 + 0] = __fadd_rn(ctx_xyz[bp * 3 + 0], __fmul_rn(__fdiv_rn(nx, denom), 0.02f));
    g_xyz_ctx[i * 3 + 1] = __fadd_rn(ctx_xyz[bp * 3 + 1], __fmul_rn(__fdiv_rn(ny, denom), 0.02f));
    g_xyz_ctx[i * 3 + 2] = __fadd_rn(ctx_xyz[bp * 3 + 2], __fmul_rn(__fdiv_rn(nz, denom), 0.02f));
}

__global__ void k_xyz_pred(const float* __restrict__ noise) {
    int i = blockIdx.x * 128 + threadIdx.x;
    if (i >= NP_TOT) return;
    float nx = noise[i * 3 + 0], ny = noise[i * 3 + 1], nz = noise[i * 3 + 2];
    float denom = __fadd_rn(sqrtf(sq3(nx, ny, nz)), 1e-6f);
    int b = i / NPRED;
    g_xyz_p[i * 3 + 0] = __fadd_rn(g_anchor[b * 3 + 0], __fmul_rn(__fdiv_rn(nx, denom), 0.05f));
    g_xyz_p[i * 3 + 1] = __fadd_rn(g_anchor[b * 3 + 1], __fmul_rn(__fdiv_rn(ny, denom), 0.05f));
    g_xyz_p[i * 3 + 2] = __fadd_rn(g_anchor[b * 3 + 2], __fmul_rn(__fdiv_rn(nz, denom), 0.05f));
}

// --------------------------------- kNN -------------------------------------
// SoA points in smem; f32x2-packed distance math (2 candidates/reg);
// 512 threads = 64 queries x 8 slices; merge buffers alias point arrays
// after the scan (sync-protected). Candidate d2 rounding matches the
// reference: sub(add(sqi,sqj), mul(2,dot)) == add(s, mul(-2,dot)) exactly.
// Strict '<' insertion scanned in ascending j preserves top_k tie-break.
template<int STAGE>  // 0: ctx (N=4608), 2: global (N=5376)
__global__ void __launch_bounds__(512) k_knn_batch() {
    constexpr int NB  = (STAGE == 0) ? NCTX : NALL;
    constexpr int QPB = 64;
    constexpr int NSL = 8;
    constexpr int SL  = NB / NSL;          // 576 / 672, both % 4 == 0, % 32 == 0
    extern __shared__ __align__(16) float smf[];
    float* sx_ = smf;
    float* sy_ = smf + NB;
    float* sz_ = smf + 2 * NB;
    float* sw_ = smf + 3 * NB;
    const float* xyz = (STAGE == 0) ? g_xyz_ctx : g_xyz_all;
    int b = blockIdx.y, base = b * NB;
    for (int j = threadIdx.x; j < NB; j += 512) {
        float x = xyz[(base + j) * 3 + 0];
        float y = xyz[(base + j) * 3 + 1];
        float z = xyz[(base + j) * 3 + 2];
        sx_[j] = x; sy_[j] = y; sz_[j] = z; sw_[j] = sq3(x, y, z);
    }
    __syncthreads();
    int qi = threadIdx.x & (QPB - 1);
    int slice = threadIdx.x / QPB;
    int q = blockIdx.x * QPB + qi;
    float qx = sx_[q], qy = sy_[q], qz = sz_[q], qw = sw_[q];
    u64 qxx = pack2(qx, qx), qyy = pack2(qy, qy), qzz = pack2(qz, qz);
    u64 qww = pack2(qw, qw);
    u64 neg2 = pack2(-2.f, -2.f);
    float bd[KK]; int bi[KK];
#pragma unroll
    for (int s = 0; s < KK; ++s) { bd[s] = 3.0e38f; bi[s] = 0; }

    auto ins = [&](float d2, int jj) {
        if (d2 < bd[KK - 1]) {
            int pos = KK - 1;
#pragma unroll
            for (int s = KK - 1; s > 0; --s)
                if (d2 < bd[s - 1]) { bd[s] = bd[s - 1]; bi[s] = bi[s - 1]; pos = s - 1; }
            bd[pos] = d2; bi[pos] = jj;
        }
    };

    int j0 = slice * SL, j1 = j0 + SL;
    // warp-uniform: SL % 32 == 0 and each warp covers a 32-aligned q range
    bool hasQ = (q >= j0) && (q < j1);

    if (!hasQ) {
        for (int j = j0; j < j1; j += 4) {
            ulonglong2 xx = *(const ulonglong2*)&sx_[j];
            ulonglong2 yy = *(const ulonglong2*)&sy_[j];
            ulonglong2 zz = *(const ulonglong2*)&sz_[j];
            ulonglong2 ww = *(const ulonglong2*)&sw_[j];
            u64 dotA = mulx2(qxx, xx.x); dotA = fma2v(qyy, yy.x, dotA); dotA = fma2v(qzz, zz.x, dotA);
            u64 dotB = mulx2(qxx, xx.y); dotB = fma2v(qyy, yy.y, dotB); dotB = fma2v(qzz, zz.y, dotB);
            u64 dA = addx2(addx2(qww, ww.x), mulx2(neg2, dotA));
            u64 dB = addx2(addx2(qww, ww.y), mulx2(neg2, dotB));
            float2 a = unpack2(dA), c = unpack2(dB);
            float m = fminf(fminf(a.x, a.y), fminf(c.x, c.y));
            if (m < bd[KK - 1]) {
                ins(a.x, j + 0); ins(a.y, j + 1);
                ins(c.x, j + 2); ins(c.y, j + 3);
            }
        }
    } else {
        for (int j = j0; j < j1; j += 4) {
            ulonglong2 xx = *(const ulonglong2*)&sx_[j];
            ulonglong2 yy = *(const ulonglong2*)&sy_[j];
            ulonglong2 zz = *(const ulonglong2*)&sz_[j];
            ulonglong2 ww = *(const ulonglong2*)&sw_[j];
            u64 dotA = mulx2(qxx, xx.x); dotA = fma2v(qyy, yy.x, dotA); dotA = fma2v(qzz, zz.x, dotA);
            u64 dotB = mulx2(qxx, xx.y); dotB = fma2v(qyy, yy.y, dotB); dotB = fma2v(qzz, zz.y, dotB);
            u64 dA = addx2(addx2(qww, ww.x), mulx2(neg2, dotA));
            u64 dB = addx2(addx2(qww, ww.y), mulx2(neg2, dotB));
            float2 a = unpack2(dA), c = unpack2(dB);
            if (j + 0 == q) a.x = 3.0e38f;
            if (j + 1 == q) a.y = 3.0e38f;
            if (j + 2 == q) c.x = 3.0e38f;
            if (j + 3 == q) c.y = 3.0e38f;
            float m = fminf(fminf(a.x, a.y), fminf(c.x, c.y));
            if (m < bd[KK - 1]) {
                ins(a.x, j + 0); ins(a.y, j + 1);
                ins(c.x, j + 2); ins(c.y, j + 3);
            }
        }
    }

    // ---- merge (buffers alias point arrays; scans done, sync-protected) ----
    __syncthreads();
    float* md = smf;                               // [NSL*KK][QPB] = 16 KB
    int*   mi = (int*)(smf + NSL * KK * QPB);      // 16 KB
#pragma unroll
    for (int s = 0; s < KK; ++s) {
        md[(slice * KK + s) * QPB + qi] = bd[s];
        mi[(slice * KK + s) * QPB + qi] = bi[s];
    }
    __syncthreads();
    if (slice == 0) {
        float fd[KK]; int fi[KK];
#pragma unroll
        for (int s = 0; s < KK; ++s) { fd[s] = 3.0e38f; fi[s] = 0; }
        for (int e = 0; e < NSL * KK; ++e) {        // slice-major = ascending j
            float d = md[e * QPB + qi];
            int  ix = mi[e * QPB + qi];
            if (d < fd[KK - 1]) {
                int pos = KK - 1;
#pragma unroll
                for (int s = KK - 1; s > 0; --s)
                    if (d < fd[s - 1]) { fd[s] = fd[s - 1]; fi[s] = fi[s - 1]; pos = s - 1; }
                fd[pos] = d; fi[pos] = ix;
            }
        }
#pragma unroll
        for (int s = 0; s < KK; ++s)
            g_idx[(base + q) * KK + s] = base + fi[s];
    }
}

// tiny 12-point graphs: one thread per query point
__global__ void k_knn_pred() {
    int i = blockIdx.x * 128 + threadIdx.x;
    if (i >= NP_TOT) return;
    int base = (i / RR) * RR;
    int lr = i - base;
    float qx = g_xyz_p[i * 3 + 0], qy = g_xyz_p[i * 3 + 1], qz = g_xyz_p[i * 3 + 2];
    float qsq = sq3(qx, qy, qz);
    float bd[KK]; int bi[KK];
#pragma unroll
    for (int s = 0; s < KK; ++s) { bd[s] = 3.0e38f; bi[s] = 0; }
    for (int j = 0; j < RR; ++j) {
        if (j == lr) continue;
        int jj = base + j;
        float px = g_xyz_p[jj * 3 + 0], py = g_xyz_p[jj * 3 + 1], pz = g_xyz_p[jj * 3 + 2];
        float psq = sq3(px, py, pz);
        float dot = __fmul_rn(qx, px);
        dot = __fmaf_rn(qy, py, dot);
        dot = __fmaf_rn(qz, pz, dot);
        float d2 = __fsub_rn(__fadd_rn(qsq, psq), __fmul_rn(2.0f, dot));
        if (d2 < bd[KK - 1]) {
            int pos = KK - 1;
#pragma unroll
            for (int s = KK - 1; s > 0; --s) {
                if (d2 < bd[s - 1]) { bd[s] = bd[s - 1]; bi[s] = bi[s - 1]; pos = s - 1; }
            }
            bd[pos] = d2; bi[pos] = j;
        }
    }
#pragma unroll
    for (int s = 0; s < KK; ++s)
        g_idx[i * KK + s] = base + bi[s];
}

// ------------------------- per-point a/b projection ------------------------
template<int MODE>   // 0 ctx, 1 pred, 2 global
__global__ void k_ab() {
    constexpr int PTS = 16;
    __shared__ __align__(16) float sx[PTS][132];
    const float* feat = (MODE == 0) ? g_ctx_feat : (MODE == 1) ? g_pred_feat : g_featAll;
    const float* xyz  = (MODE == 0) ? g_xyz_ctx  : (MODE == 1) ? g_xyz_p    : g_xyz_all;
    int i0 = blockIdx.x * PTS;
    for (int e = threadIdx.x; e < PTS * 131; e += 256) {
        int p = e / 131, t = e - p * 131;
        int i = i0 + p;
        int fr = (MODE == 2) ? i : (i / RR);
        sx[p][t] = (t < CC) ? feat[(size_t)fr * CC + t] : xyz[i * 3 + (t - CC)];
    }
    __syncthreads();
    int col = threadIdx.x;                // 0..255
    float bb = g_bab[col];
    u64 acc[PTS];
    float tacc[PTS];
    u64 init = pack2(bb, 0.f);
#pragma unroll
    for (int p = 0; p < PTS; ++p) { acc[p] = init; tacc[p] = 0.f; }
    for (int r = 0; r < 128; r += 2) {
        float w0 = g_Wab[(r + 0) * 256 + col];
        float w1 = g_Wab[(r + 1) * 256 + col];
        u64 ww = pack2(w0, w1);
#pragma unroll
        for (int p = 0; p < PTS; ++p) {
            u64 v = *(const u64*)&sx[p][r];
            ffma2(acc[p], v, ww);
        }
    }
#pragma unroll
    for (int r = 128; r < 131; ++r) {
        float w = g_Wab[r * 256 + col];
#pragma unroll
        for (int p = 0; p < PTS; ++p) tacc[p] = fmaf(sx[p][r], w, tacc[p]);
    }
#pragma unroll
    for (int p = 0; p < PTS; ++p) {
        float2 u = unpack2(acc[p]);
        float res = u.x + u.y + tacc[p];
        int i = i0 + p;
        if (col < CC) g_a[(size_t)i * CC + col] = res;
        else          g_b[(size_t)i * CC + (col - CC)] = res;
    }
}

// --------------------- EdgeConv layer 2 + max aggregate --------------------
template<int MODE>
__global__ void __launch_bounds__(128) k_edge(const float* __restrict__ We2,
                                              const float* __restrict__ be2) {
    constexpr int PTS = 8;
    __shared__ __align__(16) float shid[128 * 68];    // [h][e], stride 68
    int i0 = blockIdx.x * PTS;
    int tid = threadIdx.x;
#pragma unroll
    for (int p = 0; p < PTS; ++p) {
        int i = i0 + p;
        float av = g_a[(size_t)i * CC + tid];
#pragma unroll
        for (int j = 0; j < KK; ++j) {
            int nb = g_idx[i * KK + j];
            float bv = g_b[(size_t)nb * CC + tid];
            shid[tid * 68 + p * KK + j] = fmaxf(__fadd_rn(av, bv), 0.f);
        }
    }
    __syncthreads();
    u64 acc[32];
#pragma unroll
    for (int e = 0; e < 32; ++e) acc[e] = 0ull;
    for (int h = 0; h < 128; ++h) {
        float w = We2[h * CC + tid];
        u64 ww = pack2(w, w);
        const ulonglong2* hp = (const ulonglong2*)&shid[h * 68];
#pragma unroll
        for (int e = 0; e < 16; ++e) {
            ulonglong2 v = hp[e];
            ffma2(acc[2 * e + 0], v.x, ww);
            ffma2(acc[2 * e + 1], v.y, ww);
        }
    }
    float bb = be2[tid];
#pragma unroll
    for (int p = 0; p < PTS; ++p) {
        float2 v0 = unpack2(acc[p * 4 + 0]);
        float2 v1 = unpack2(acc[p * 4 + 1]);
        float2 v2 = unpack2(acc[p * 4 + 2]);
        float2 v3 = unpack2(acc[p * 4 + 3]);
        float mx = fmaxf(fmaxf(fmaxf(v0.x, v0.y), fmaxf(v1.x, v1.y)),
                         fmaxf(fmaxf(v2.x, v2.y), fmaxf(v3.x, v3.y)));
        g_featAll[(size_t)mapOut<MODE>(i0 + p) * CC + tid] = mx + bb;
    }
}

// ------------------------------ offset MLP ---------------------------------
template<int MODE>
__global__ void __launch_bounds__(128) k_offset(const float* __restrict__ W1,
                                                const float* __restrict__ b1,
                                                const float* __restrict__ W2,
                                                const float* __restrict__ b2,
                                                float* __restrict__ outp) {
    constexpr int PTS = 8;
    __shared__ __align__(16) float sf[PTS][CC];
    __shared__ float sh[PTS][CC];
    int i0 = blockIdx.x * PTS, tid = threadIdx.x;
#pragma unroll
    for (int p = 0; p < PTS; ++p)
        sf[p][tid] = g_featAll[(size_t)mapOut<MODE>(i0 + p) * CC + tid];
    __syncthreads();
    float bb = b1[tid];
    u64 acc[PTS];
    u64 init = pack2(bb, 0.f);
#pragma unroll
    for (int p = 0; p < PTS; ++p) acc[p] = init;
    for (int r = 0; r < CC; r += 2) {
        u64 ww = pack2(W1[(r + 0) * CC + tid], W1[(r + 1) * CC + tid]);
#pragma unroll
        for (int p = 0; p < PTS; ++p) {
            u64 v = *(const u64*)&sf[p][r];
            ffma2(acc[p], v, ww);
        }
    }
#pragma unroll
    for (int p = 0; p < PTS; ++p) {
        float2 u = unpack2(acc[p]);
        sh[p][tid] = fmaxf(u.x + u.y, 0.f);
    }
    __syncthreads();
    int wp0 = (tid >> 5) * 2, l = tid & 31;
#pragma unroll
    for (int t = 0; t < 2; ++t) {
        int wp = wp0 + t;
        int i = i0 + wp;
        float s0 = 0.f, s1 = 0.f, s2 = 0.f;
        for (int h = l; h < CC; h += 32) {
            float hv = sh[wp][h];
            s0 = fmaf(hv, W2[h * 3 + 0], s0);
            s1 = fmaf(hv, W2[h * 3 + 1], s1);
            s2 = fmaf(hv, W2[h * 3 + 2], s2);
        }
#pragma unroll
        for (int off = 16; off; off >>= 1) {
            s0 += __shfl_down_sync(0xffffffffu, s0, off);
            s1 += __shfl_down_sync(0xffffffffu, s1, off);
            s2 += __shfl_down_sync(0xffffffffu, s2, off);
        }
        if (l == 0) {
            const float* xin = (MODE == 0) ? g_xyz_ctx : (MODE == 1) ? g_xyz_p : g_xyz_all;
            float* orow;
            if (MODE == 2) orow = outp + (size_t)i * 3;
            else           orow = g_xyz_all + (size_t)mapOut<MODE>(i) * 3;
            orow[0] = xin[i * 3 + 0] + s0 + b2[0];
            orow[1] = xin[i * 3 + 1] + s1 + b2[1];
            orow[2] = xin[i * 3 + 2] + s2 + b2[2];
        }
    }
}

// ------------------------------- launcher ----------------------------------
extern "C" void kernel_launch(void* const* d_in, const int* in_sizes, int n_in,
                              void* d_out, int out_size) {
    const float* ctx_xyz     = (const float*)d_in[0];
    const float* ctx_tokens  = (const float*)d_in[1];
    const float* pred_tokens = (const float*)d_in[2];
    const float* noise_ctx   = (const float*)d_in[3];
    const float* noise_pred  = (const float*)d_in[4];
    const float* Wp  = (const float*)d_in[5];
    const float* bp  = (const float*)d_in[6];
    const float* We1 = (const float*)d_in[7];
    const float* be1 = (const float*)d_in[8];
    const float* We2 = (const float*)d_in[9];
    const float* be2 = (const float*)d_in[10];
    const float* Wc1 = (const float*)d_in[11];
    const float* bc1 = (const float*)d_in[12];
    const float* Wc2 = (const float*)d_in[13];
    const float* bc2 = (const float*)d_in[14];
    const float* Wq1 = (const float*)d_in[15];
    const float* bq1 = (const float*)d_in[16];
    const float* Wq2 = (const float*)d_in[17];
    const float* bq2 = (const float*)d_in[18];
    const float* Wf1 = (const float*)d_in[19];
    const float* bf1 = (const float*)d_in[20];
    const float* Wf2 = (const float*)d_in[21];
    const float* bf2 = (const float*)d_in[22];
    (void)in_sizes; (void)n_in; (void)out_size;
    float* out = (float*)d_out;

    constexpr int SM_KNN0 = NCTX * 16;   // 73728  -> 3 blocks/SM
    constexpr int SM_KNN2 = NALL * 16;   // 86016  -> 2 blocks/SM
    cudaFuncSetAttribute(k_knn_batch<0>, cudaFuncAttributeMaxDynamicSharedMemorySize, SM_KNN0);
    cudaFuncSetAttribute(k_knn_batch<2>, cudaFuncAttributeMaxDynamicSharedMemorySize, SM_KNN2);

    // launch 4 == ncu-captured slot -> k_ab<0> this round
    k_wab<<<(131 * 128 + 255) / 256, 256>>>(We1, be1);              // 1
    k_proj<0><<<BB * PP / 8, 128>>>(ctx_tokens, Wp, bp);            // 2
    k_xyz_ctx<<<NC_TOT / 128, 128>>>(ctx_xyz, noise_ctx);           // 3
    k_ab<0><<<NC_TOT / 16, 256>>>();                                // 4  (profiled)
    k_anchor<<<BB, 128>>>(ctx_xyz);                                 // 5
    k_xyz_pred<<<NP_TOT / 128, 128>>>(noise_pred);                  // 6
    k_knn_batch<0><<<dim3(NCTX / 64, BB), 512, SM_KNN0>>>();        // 7
    k_proj<1><<<BB * MMH / 8, 128>>>(pred_tokens, Wp, bp);          // 8

    // ---- context branch ----
    k_edge<0><<<NC_TOT / 8, 128>>>(We2, be2);
    k_offset<0><<<NC_TOT / 8, 128>>>(Wc1, bc1, Wc2, bc2, nullptr);

    // ---- prediction branch ----
    k_knn_pred<<<NP_TOT / 128, 128>>>();
    k_ab<1><<<NP_TOT / 16, 256>>>();
    k_edge<1><<<NP_TOT / 8, 128>>>(We2, be2);
    k_offset<1><<<NP_TOT / 8, 128>>>(Wq1, bq1, Wq2, bq2, nullptr);

    // ---- global refinement ----
    k_knn_batch<2><<<dim3(NALL / 64, BB), 512, SM_KNN2>>>();
    k_ab<2><<<NA_TOT / 16, 256>>>();
    k_edge<2><<<NA_TOT / 8, 128>>>(We2, be2);
    k_offset<2><<<NA_TOT / 8, 128>>>(Wf1, bf1, Wf2, bf2, out);
}